// round 2
// baseline (speedup 1.0000x reference)
#include <cuda_runtime.h>

#define NT 192
#define NSTEPS 16
#define DT (1.0f/16.0f)

__device__ __forceinline__ float dot8(const float* a, const float* b) {
    float s0 = a[0]*b[0];
    float s1 = a[1]*b[1];
    s0 = fmaf(a[2], b[2], s0);  s1 = fmaf(a[3], b[3], s1);
    s0 = fmaf(a[4], b[4], s0);  s1 = fmaf(a[5], b[5], s1);
    s0 = fmaf(a[6], b[6], s0);  s1 = fmaf(a[7], b[7], s1);
    return s0 + s1;
}

extern "C" __global__ void __launch_bounds__(NT, 1)
adj_lie_kernel(const float* __restrict__ U0, const float* __restrict__ eps,
               const float* __restrict__ W0, const float* __restrict__ W1,
               const float* __restrict__ W2, float* __restrict__ out, int B)
{
    extern __shared__ float sh[];
    float* w2s  = sh;               // 64: W2 row-major (broadcast reads)
    float* w0a  = sh + 64;          // 64: antisym(W0)
    float* w1a  = sh + 128;         // 64: antisym(W1)
    float* svb  = sh + 192;                 // [64][NT] : v  (eps)
    float* sbvb = svb  + 64*NT;             // [64][NT] : Bv = v*W2
    float* subb = sbvb + 64*NT;             // [64][NT] : U base
    float* sacb = subb + 64*NT;             // [64][NT] : RK4 accumulator

    const int tid  = threadIdx.x;
    const int gtid = blockIdx.x * NT + tid;

    if (tid < 64) {
        int i = tid >> 3, j = tid & 7;
        w2s[tid] = W2[tid];
        w0a[tid] = 0.5f * (W0[i*8+j] - W0[j*8+i]);
        w1a[tid] = 0.5f * (W1[i*8+j] - W1[j*8+i]);
    }
    __syncthreads();

    if (gtid >= B) return;

    float* sv  = svb  + tid;
    float* sbv = sbvb + tid;
    float* sub = subb + tid;
    float* sac = sacb + tid;

    // ---- load U0 (regs + shared base) and eps (shared) ----
    float Ue[64];
    {
        const float4* u4 = (const float4*)(U0  + (size_t)gtid * 64);
        const float4* e4 = (const float4*)(eps + (size_t)gtid * 64);
        #pragma unroll
        for (int e = 0; e < 16; e++) {
            float4 u = u4[e];
            Ue[4*e+0] = u.x; Ue[4*e+1] = u.y; Ue[4*e+2] = u.z; Ue[4*e+3] = u.w;
            float4 v = e4[e];
            sv[(4*e+0)*NT] = v.x; sv[(4*e+1)*NT] = v.y;
            sv[(4*e+2)*NT] = v.z; sv[(4*e+3)*NT] = v.w;
        }
        #pragma unroll
        for (int e = 0; e < 64; e++) sub[e*NT] = Ue[e];
    }

    // ---- Bv = v * W2 (constant over the whole integration) ----
    {
        float Bv[64];
        #pragma unroll
        for (int k = 0; k < 8; k++) {
            float w[8];
            float4 wa = *(const float4*)(w2s + k*8);
            float4 wb = *(const float4*)(w2s + k*8 + 4);
            w[0]=wa.x; w[1]=wa.y; w[2]=wa.z; w[3]=wa.w;
            w[4]=wb.x; w[5]=wb.y; w[6]=wb.z; w[7]=wb.w;
            #pragma unroll
            for (int i = 0; i < 8; i++) {
                float vik = sv[(i*8+k)*NT];
                #pragma unroll
                for (int j = 0; j < 8; j++) {
                    if (k == 0) Bv[i*8+j] = vik * w[j];
                    else        Bv[i*8+j] = fmaf(vik, w[j], Bv[i*8+j]);
                }
            }
        }
        #pragma unroll
        for (int e = 0; e < 64; e++) sbv[e*NT] = Bv[e];
    }

    float logj = 0.0f;
    float lacc = 0.0f;

    #pragma unroll 1
    for (int step = 0; step < NSTEPS; step++) {
        float t0 = (float)step * DT;
        #pragma unroll 1
        for (int s = 0; s < 4; s++) {
            float t = t0 + ((s == 0) ? 0.0f : (s == 3 ? DT : 0.5f*DT));

            // ================= rhs(t, Ue) =================
            // A = Ue * W2
            float A[64];
            #pragma unroll
            for (int k = 0; k < 8; k++) {
                float w[8];
                float4 wa = *(const float4*)(w2s + k*8);
                float4 wb = *(const float4*)(w2s + k*8 + 4);
                w[0]=wa.x; w[1]=wa.y; w[2]=wa.z; w[3]=wa.w;
                w[4]=wb.x; w[5]=wb.y; w[6]=wb.z; w[7]=wb.w;
                #pragma unroll
                for (int i = 0; i < 8; i++) {
                    float u = Ue[i*8+k];
                    #pragma unroll
                    for (int j = 0; j < 8; j++) {
                        if (k == 0) A[i*8+j] = u * w[j];
                        else        A[i*8+j] = fmaf(u, w[j], A[i*8+j]);
                    }
                }
            }

            // P = Ue * v^T  (P[i][j] = <Ue_i, v_j>), then R = 0.5*(P^T - P) in place
            float Rm[64];
            #pragma unroll
            for (int j = 0; j < 8; j++) {
                float vj[8];
                #pragma unroll
                for (int k = 0; k < 8; k++) vj[k] = sv[(j*8+k)*NT];
                #pragma unroll
                for (int i = 0; i < 8; i++)
                    Rm[i*8+j] = dot8(&Ue[i*8], vj);
            }
            #pragma unroll
            for (int i = 0; i < 8; i++) {
                Rm[i*8+i] = 0.0f;
                #pragma unroll
                for (int j = i+1; j < 8; j++) {
                    float r = 0.5f * (Rm[j*8+i] - Rm[i*8+j]);
                    Rm[i*8+j] =  r;
                    Rm[j*8+i] = -r;
                }
            }

            // s1 = <Bv, R*Ue>
            float s1a = 0.0f, s1b = 0.0f;
            #pragma unroll
            for (int i = 0; i < 8; i++) {
                float bi[8];
                #pragma unroll
                for (int m = 0; m < 8; m++) bi[m] = sbv[(i*8+m)*NT];
                #pragma unroll
                for (int k = 0; k < 8; k++) {
                    float g = dot8(&Ue[k*8], bi);
                    if (k & 1) s1b = fmaf(Rm[i*8+k], g, s1b);
                    else       s1a = fmaf(Rm[i*8+k], g, s1a);
                }
            }
            // s2 = <A, R*v>
            float s2a = 0.0f, s2b = 0.0f;
            #pragma unroll
            for (int k = 0; k < 8; k++) {
                float vk[8];
                #pragma unroll
                for (int m = 0; m < 8; m++) vk[m] = sv[(k*8+m)*NT];
                #pragma unroll
                for (int i = 0; i < 8; i++) {
                    float g = dot8(&A[i*8], vk);
                    if (i & 1) s2b = fmaf(Rm[i*8+k], g, s2b);
                    else       s2a = fmaf(Rm[i*8+k], g, s2a);
                }
            }
            float kl = (s1a + s1b) + (s2a + s2b);
            // Rm dead from here — its registers are reused for Fm below.

            // F = antisym(A * Ue^T) + w0a + t*w1a
            float Fm[64];
            #pragma unroll
            for (int i = 0; i < 8; i++) Fm[i*8+i] = 0.0f;
            #pragma unroll
            for (int i = 0; i < 8; i++) {
                #pragma unroll
                for (int j = i+1; j < 8; j++) {
                    float mij = dot8(&A[i*8], &Ue[j*8]);
                    float mji = dot8(&A[j*8], &Ue[i*8]);
                    float f = fmaf(t, w1a[i*8+j], 0.5f*(mij - mji) + w0a[i*8+j]);
                    Fm[i*8+j] =  f;
                    Fm[j*8+i] = -f;
                }
            }
            // A dead from here — registers reused for vel.

            // vel = F * Ue
            float vel[64];
            #pragma unroll
            for (int k = 0; k < 8; k++) {
                #pragma unroll
                for (int i = 0; i < 8; i++) {
                    float f = Fm[i*8+k];
                    #pragma unroll
                    for (int m = 0; m < 8; m++) {
                        if (k == 0) vel[i*8+m] = f * Ue[k*8+m];
                        else        vel[i*8+m] = fmaf(f, Ue[k*8+m], vel[i*8+m]);
                    }
                }
            }
            // ================= end rhs =================

            if (s == 0) {
                lacc = kl;
                #pragma unroll
                for (int e = 0; e < 64; e++) {
                    sac[e*NT] = vel[e];
                    Ue[e] = fmaf(0.5f*DT, vel[e], Ue[e]);   // Ue was U base at s==0
                }
            } else if (s == 1) {
                lacc = fmaf(2.0f, kl, lacc);
                #pragma unroll
                for (int e = 0; e < 64; e++) {
                    sac[e*NT] = fmaf(2.0f, vel[e], sac[e*NT]);
                    Ue[e] = fmaf(0.5f*DT, vel[e], sub[e*NT]);
                }
            } else if (s == 2) {
                lacc = fmaf(2.0f, kl, lacc);
                #pragma unroll
                for (int e = 0; e < 64; e++) {
                    sac[e*NT] = fmaf(2.0f, vel[e], sac[e*NT]);
                    Ue[e] = fmaf(DT, vel[e], sub[e*NT]);
                }
            } else {
                logj = fmaf(DT/6.0f, lacc + kl, logj);
                #pragma unroll
                for (int e = 0; e < 64; e++) {
                    float un = fmaf(DT/6.0f, sac[e*NT] + vel[e], sub[e*NT]);
                    Ue[e] = un;
                    sub[e*NT] = un;
                }
            }
        }
    }

    // ---- write outputs: U then logj ----
    {
        float4* o4 = (float4*)(out + (size_t)gtid * 64);
        #pragma unroll
        for (int e = 0; e < 16; e++) {
            float4 u;
            u.x = Ue[4*e+0]; u.y = Ue[4*e+1]; u.z = Ue[4*e+2]; u.w = Ue[4*e+3];
            o4[e] = u;
        }
        out[(size_t)B * 64 + gtid] = logj;
    }
}

extern "C" void kernel_launch(void* const* d_in, const int* in_sizes, int n_in,
                              void* d_out, int out_size)
{
    const float* U0  = (const float*)d_in[0];
    const float* eps = (const float*)d_in[1];
    const float* W0  = (const float*)d_in[2];
    const float* W1  = (const float*)d_in[3];
    const float* W2  = (const float*)d_in[4];
    float* out = (float*)d_out;

    int B = in_sizes[0] / 64;
    size_t shmem = (size_t)(192 + 4 * 64 * NT) * sizeof(float);   // ~193 KB
    cudaFuncSetAttribute(adj_lie_kernel,
                         cudaFuncAttributeMaxDynamicSharedMemorySize, (int)shmem);
    int grid = (B + NT - 1) / NT;
    adj_lie_kernel<<<grid, NT, shmem>>>(U0, eps, W0, W1, W2, out, B);
}

// round 3
// speedup vs baseline: 1.1281x; 1.1281x over previous
#include <cuda_runtime.h>

typedef unsigned long long ull;

#define NT 192
#define NSTEPS 16
#define DT (1.0f/16.0f)
// upper-triangle index for i<j, 8x8
#define TRI(i,j) ((i)*7 - (i)*((i)-1)/2 + (j) - (i) - 1)

__device__ __forceinline__ ull fma2(ull a, ull b, ull c){
    ull d; asm("fma.rn.f32x2 %0,%1,%2,%3;" : "=l"(d) : "l"(a),"l"(b),"l"(c)); return d;
}
__device__ __forceinline__ ull mul2(ull a, ull b){
    ull d; asm("mul.rn.f32x2 %0,%1,%2;" : "=l"(d) : "l"(a),"l"(b)); return d;
}
__device__ __forceinline__ ull add2(ull a, ull b){
    ull d; asm("add.rn.f32x2 %0,%1,%2;" : "=l"(d) : "l"(a),"l"(b)); return d;
}
__device__ __forceinline__ float hsum2(ull a){
    float lo,hi; asm("mov.b64 {%0,%1},%2;" : "=f"(lo),"=f"(hi) : "l"(a)); return lo+hi;
}
__device__ __forceinline__ ull dup_f(float x){
    ull r; asm("mov.b64 %0,{%1,%1};" : "=l"(r) : "f"(x)); return r;
}
__device__ __forceinline__ ull dup_lo(ull a){
    ull r; asm("{.reg .f32 l,h; mov.b64 {l,h},%1; mov.b64 %0,{l,l};}" : "=l"(r) : "l"(a)); return r;
}
__device__ __forceinline__ ull dup_hi(ull a){
    ull r; asm("{.reg .f32 l,h; mov.b64 {l,h},%1; mov.b64 %0,{h,h};}" : "=l"(r) : "l"(a)); return r;
}
// packed dot of two 8-float rows (4 ull each): returns packed partial sums
__device__ __forceinline__ ull dotp(const ull* a, const ull* b){
    ull s = mul2(a[0],b[0]);
    s = fma2(a[1],b[1],s);
    s = fma2(a[2],b[2],s);
    s = fma2(a[3],b[3],s);
    return s;
}

extern "C" __global__ void __launch_bounds__(NT, 1)
adj_lie_kernel(const float* __restrict__ U0, const float* __restrict__ eps,
               const float* __restrict__ W0, const float* __restrict__ W1,
               const float* __restrict__ W2, float* __restrict__ out, int B)
{
    extern __shared__ ull shl[];
    ull*   w2p = shl;                   // 32 ull : W2 rows, packed pairs (broadcast)
    float* w0a = (float*)(shl + 32);    // 64 f   : antisym(W0)
    float* w1a = (float*)(shl + 64);    // 64 f   : antisym(W1)
    ull* svb  = shl + 96;               // [32][NT] : v (eps), packed
    ull* sbvb = svb  + 32*NT;           // [32][NT] : Bv = v*W2, packed
    ull* subb = sbvb + 32*NT;           // [32][NT] : U base, packed
    ull* sacb = subb + 32*NT;           // [32][NT] : RK4 accumulator, packed

    const int tid  = threadIdx.x;
    const int gtid = blockIdx.x * NT + tid;

    if (tid < 32) w2p[tid] = ((const ull*)W2)[tid];
    if (tid < 64) {
        int i = tid >> 3, j = tid & 7;
        w0a[tid] = 0.5f * (W0[i*8+j] - W0[j*8+i]);
        w1a[tid] = 0.5f * (W1[i*8+j] - W1[j*8+i]);
    }
    __syncthreads();

    if (gtid >= B) return;

    ull* sv  = svb  + tid;
    ull* sbv = sbvb + tid;
    ull* sub = subb + tid;
    ull* sac = sacb + tid;

    // ---- load U0 (regs + shared base) and eps (shared), already pair-packed in memory ----
    ull UeP[32];
    {
        const ulonglong2* u2 = (const ulonglong2*)(U0  + (size_t)gtid * 64);
        const ulonglong2* e2 = (const ulonglong2*)(eps + (size_t)gtid * 64);
        #pragma unroll
        for (int e = 0; e < 16; e++) {
            ulonglong2 u = u2[e];
            UeP[2*e] = u.x; UeP[2*e+1] = u.y;
            ulonglong2 v = e2[e];
            sv[(2*e)*NT] = v.x; sv[(2*e+1)*NT] = v.y;
        }
        #pragma unroll
        for (int c = 0; c < 32; c++) sub[c*NT] = UeP[c];
    }

    // ---- Bv = v * W2 (constant over the whole integration) ----
    #pragma unroll
    for (int i = 0; i < 8; i++) {
        ull vi[4];
        #pragma unroll
        for (int c = 0; c < 4; c++) vi[c] = sv[(i*4+c)*NT];
        ull acc[4];
        #pragma unroll
        for (int k = 0; k < 8; k++) {
            ull d = (k & 1) ? dup_hi(vi[k>>1]) : dup_lo(vi[k>>1]);
            #pragma unroll
            for (int c = 0; c < 4; c++) {
                ull w = w2p[k*4+c];
                acc[c] = (k == 0) ? mul2(d, w) : fma2(d, w, acc[c]);
            }
        }
        #pragma unroll
        for (int c = 0; c < 4; c++) sbv[(i*4+c)*NT] = acc[c];
    }

    float logj = 0.0f, lacc = 0.0f;

    #pragma unroll 1
    for (int step = 0; step < NSTEPS; step++) {
        float t0 = (float)step * DT;
        #pragma unroll 1
        for (int s = 0; s < 4; s++) {
            float t = t0 + ((s == 0) ? 0.0f : (s == 3 ? DT : 0.5f*DT));

            // ========== A = Ue * W2 ==========
            ull AP[32];
            #pragma unroll
            for (int k = 0; k < 8; k++) {
                #pragma unroll
                for (int i = 0; i < 8; i++) {
                    ull d = (k & 1) ? dup_hi(UeP[i*4+(k>>1)]) : dup_lo(UeP[i*4+(k>>1)]);
                    #pragma unroll
                    for (int c = 0; c < 4; c++) {
                        ull w = w2p[k*4+c];
                        if (k == 0) AP[i*4+c] = mul2(d, w);
                        else        AP[i*4+c] = fma2(d, w, AP[i*4+c]);
                    }
                }
            }

            // ========== R' = (P^T - P) (unscaled) fused with s2 = <A, R v> ==========
            // R'[i][j] = <Ue_j, v_i> - <Ue_i, v_j>  for i<j
            // s2' accumulates Sum R'ij * (<A_i,v_j> - <A_j,v_i>) in packed form
            float Rt[28];
            ull s2a = 0ull, s2b = 0ull;
            #pragma unroll
            for (int i = 0; i < 8; i++) {
                ull vi[4];
                #pragma unroll
                for (int c = 0; c < 4; c++) vi[c] = sv[(i*4+c)*NT];
                #pragma unroll
                for (int j = i+1; j < 8; j++) {
                    ull vj[4];
                    #pragma unroll
                    for (int c = 0; c < 4; c++) vj[c] = sv[(j*4+c)*NT];
                    ull p1 = dotp(&UeP[j*4], vi);
                    ull p2 = dotp(&UeP[i*4], vj);
                    float r = hsum2(p1) - hsum2(p2);
                    Rt[TRI(i,j)] = r;
                    ull rd = dup_f(r);
                    ull q1 = dotp(&AP[i*4], vj);
                    ull q2 = dotp(&AP[j*4], vi);
                    s2a = fma2(rd, q1, s2a);
                    s2b = fma2(rd, q2, s2b);
                }
            }

            // ========== s1 = <Bv, R Ue> ==========
            ull s1a = 0ull, s1b = 0ull;
            #pragma unroll
            for (int i = 0; i < 8; i++) {
                ull bi[4];
                #pragma unroll
                for (int c = 0; c < 4; c++) bi[c] = sbv[(i*4+c)*NT];
                #pragma unroll
                for (int j = i+1; j < 8; j++) {
                    ull bj[4];
                    #pragma unroll
                    for (int c = 0; c < 4; c++) bj[c] = sbv[(j*4+c)*NT];
                    ull rd = dup_f(Rt[TRI(i,j)]);
                    ull q1 = dotp(&UeP[j*4], bi);
                    ull q2 = dotp(&UeP[i*4], bj);
                    s1a = fma2(rd, q1, s1a);
                    s1b = fma2(rd, q2, s1b);
                }
            }
            float kl = 0.5f * ((hsum2(s1a) - hsum2(s1b)) + (hsum2(s2a) - hsum2(s2b)));

            // ========== F = antisym(A Ue^T) + w0a + t*w1a, vel = F*Ue (incremental) ==========
            ull velP[32];
            #pragma unroll
            for (int c = 0; c < 32; c++) velP[c] = 0ull;
            #pragma unroll
            for (int i = 0; i < 8; i++) {
                #pragma unroll
                for (int j = i+1; j < 8; j++) {
                    ull m1 = dotp(&AP[i*4], &UeP[j*4]);   // M[i][j]
                    ull m2 = dotp(&AP[j*4], &UeP[i*4]);   // M[j][i]
                    float f = fmaf(t, w1a[i*8+j],
                                   fmaf(0.5f, hsum2(m1) - hsum2(m2), w0a[i*8+j]));
                    ull fd = dup_f(f);
                    ull fn = dup_f(-f);
                    #pragma unroll
                    for (int c = 0; c < 4; c++) {
                        velP[i*4+c] = fma2(fd, UeP[j*4+c], velP[i*4+c]);
                        velP[j*4+c] = fma2(fn, UeP[i*4+c], velP[j*4+c]);
                    }
                }
            }
            // ========== end rhs ==========

            if (s == 0) {
                lacc = kl;
                const ull hdt = dup_f(0.5f*DT);
                #pragma unroll
                for (int c = 0; c < 32; c++) {
                    sac[c*NT] = velP[c];
                    UeP[c] = fma2(hdt, velP[c], UeP[c]);     // UeP was U base
                }
            } else if (s == 1) {
                lacc = fmaf(2.0f, kl, lacc);
                const ull two = dup_f(2.0f), hdt = dup_f(0.5f*DT);
                #pragma unroll
                for (int c = 0; c < 32; c++) {
                    sac[c*NT] = fma2(two, velP[c], sac[c*NT]);
                    UeP[c] = fma2(hdt, velP[c], sub[c*NT]);
                }
            } else if (s == 2) {
                lacc = fmaf(2.0f, kl, lacc);
                const ull two = dup_f(2.0f), fdt = dup_f(DT);
                #pragma unroll
                for (int c = 0; c < 32; c++) {
                    sac[c*NT] = fma2(two, velP[c], sac[c*NT]);
                    UeP[c] = fma2(fdt, velP[c], sub[c*NT]);
                }
            } else {
                logj = fmaf(DT/6.0f, lacc + kl, logj);
                const ull d6 = dup_f(DT/6.0f);
                #pragma unroll
                for (int c = 0; c < 32; c++) {
                    ull un = fma2(d6, add2(sac[c*NT], velP[c]), sub[c*NT]);
                    UeP[c] = un;
                    sub[c*NT] = un;
                }
            }
        }
    }

    // ---- write outputs: U then logj ----
    {
        ulonglong2* o2 = (ulonglong2*)(out + (size_t)gtid * 64);
        #pragma unroll
        for (int e = 0; e < 16; e++) {
            ulonglong2 w;
            w.x = UeP[2*e]; w.y = UeP[2*e+1];
            o2[e] = w;
        }
        out[(size_t)B * 64 + gtid] = logj;
    }
}

extern "C" void kernel_launch(void* const* d_in, const int* in_sizes, int n_in,
                              void* d_out, int out_size)
{
    const float* U0  = (const float*)d_in[0];
    const float* eps = (const float*)d_in[1];
    const float* W0  = (const float*)d_in[2];
    const float* W1  = (const float*)d_in[3];
    const float* W2  = (const float*)d_in[4];
    float* out = (float*)d_out;

    int B = in_sizes[0] / 64;
    size_t shmem = (size_t)(96 + 4 * 32 * NT) * sizeof(ull);   // ~193 KB
    cudaFuncSetAttribute(adj_lie_kernel,
                         cudaFuncAttributeMaxDynamicSharedMemorySize, (int)shmem);
    int grid = (B + NT - 1) / NT;
    adj_lie_kernel<<<grid, NT, shmem>>>(U0, eps, W0, W1, W2, out, B);
}

// round 6
// speedup vs baseline: 1.1304x; 1.0020x over previous
#include <cuda_runtime.h>

typedef unsigned long long ull;

#define NT 192
#define NSTEPS 16
#define DT (1.0f/16.0f)
// upper-triangle index for i<j, 8x8
#define TRI(i,j) ((i)*7 - (i)*((i)-1)/2 + (j) - (i) - 1)

__device__ __forceinline__ ull fma2(ull a, ull b, ull c){
    ull d; asm("fma.rn.f32x2 %0,%1,%2,%3;" : "=l"(d) : "l"(a),"l"(b),"l"(c)); return d;
}
__device__ __forceinline__ ull mul2(ull a, ull b){
    ull d; asm("mul.rn.f32x2 %0,%1,%2;" : "=l"(d) : "l"(a),"l"(b)); return d;
}
__device__ __forceinline__ ull add2(ull a, ull b){
    ull d; asm("add.rn.f32x2 %0,%1,%2;" : "=l"(d) : "l"(a),"l"(b)); return d;
}
__device__ __forceinline__ float hsum2(ull a){
    float lo,hi; asm("mov.b64 {%0,%1},%2;" : "=f"(lo),"=f"(hi) : "l"(a)); return lo+hi;
}
__device__ __forceinline__ ull dup_f(float x){
    ull r; asm("mov.b64 %0,{%1,%1};" : "=l"(r) : "f"(x)); return r;
}
__device__ __forceinline__ ull dup_lo(ull a){
    ull r; asm("{.reg .f32 l,h; mov.b64 {l,h},%1; mov.b64 %0,{l,l};}" : "=l"(r) : "l"(a)); return r;
}
__device__ __forceinline__ ull dup_hi(ull a){
    ull r; asm("{.reg .f32 l,h; mov.b64 {l,h},%1; mov.b64 %0,{h,h};}" : "=l"(r) : "l"(a)); return r;
}
// packed dot of two 8-float rows (4 ull each): returns packed partial sums
__device__ __forceinline__ ull dotp(const ull* a, const ull* b){
    ull s = mul2(a[0],b[0]);
    s = fma2(a[1],b[1],s);
    s = fma2(a[2],b[2],s);
    s = fma2(a[3],b[3],s);
    return s;
}

extern "C" __global__ void __launch_bounds__(NT, 1)
adj_lie_kernel(const float* __restrict__ U0, const float* __restrict__ eps,
               const float* __restrict__ W0, const float* __restrict__ W1,
               const float* __restrict__ W2, float* __restrict__ out, int B)
{
    extern __shared__ ull shl[];
    ull*   w2p = shl;                   // 32 ull : W2 rows, packed pairs (broadcast)
    float* w0a = (float*)(shl + 32);    // 64 f   : antisym(W0)
    float* w1a = (float*)(shl + 64);    // 64 f   : antisym(W1)
    ull* svb  = shl + 96;               // [32][NT] : v (eps), packed
    ull* sbvb = svb  + 32*NT;           // [32][NT] : Bv = v*W2, packed
    ull* subb = sbvb + 32*NT;           // [32][NT] : U base, packed
    ull* sacb = subb + 32*NT;           // [32][NT] : RK4 accumulator, packed

    const int tid  = threadIdx.x;
    const int gtid = blockIdx.x * NT + tid;

    if (tid < 32) w2p[tid] = ((const ull*)W2)[tid];
    if (tid < 64) {
        int i = tid >> 3, j = tid & 7;
        w0a[tid] = 0.5f * (W0[i*8+j] - W0[j*8+i]);
        w1a[tid] = 0.5f * (W1[i*8+j] - W1[j*8+i]);
    }
    __syncthreads();

    if (gtid >= B) return;

    ull* sv  = svb  + tid;
    ull* sbv = sbvb + tid;
    ull* sub = subb + tid;
    ull* sac = sacb + tid;

    // ---- load U0 (regs + shared base) and eps (shared), already pair-packed in memory ----
    ull UeP[32];
    {
        const ulonglong2* u2 = (const ulonglong2*)(U0  + (size_t)gtid * 64);
        const ulonglong2* e2 = (const ulonglong2*)(eps + (size_t)gtid * 64);
        #pragma unroll
        for (int e = 0; e < 16; e++) {
            ulonglong2 u = u2[e];
            UeP[2*e] = u.x; UeP[2*e+1] = u.y;
            ulonglong2 v = e2[e];
            sv[(2*e)*NT] = v.x; sv[(2*e+1)*NT] = v.y;
        }
        #pragma unroll
        for (int c = 0; c < 32; c++) sub[c*NT] = UeP[c];
    }

    // ---- Bv = v * W2 (constant over the whole integration) ----
    #pragma unroll
    for (int i = 0; i < 8; i++) {
        ull vi[4];
        #pragma unroll
        for (int c = 0; c < 4; c++) vi[c] = sv[(i*4+c)*NT];
        ull acc[4];
        #pragma unroll
        for (int k = 0; k < 8; k++) {
            ull d = (k & 1) ? dup_hi(vi[k>>1]) : dup_lo(vi[k>>1]);
            #pragma unroll
            for (int c = 0; c < 4; c++) {
                ull w = w2p[k*4+c];
                acc[c] = (k == 0) ? mul2(d, w) : fma2(d, w, acc[c]);
            }
        }
        #pragma unroll
        for (int c = 0; c < 4; c++) sbv[(i*4+c)*NT] = acc[c];
    }

    float logj = 0.0f, lacc = 0.0f;

    #pragma unroll 1
    for (int step = 0; step < NSTEPS; step++) {
        float t0 = (float)step * DT;
        #pragma unroll 1
        for (int s = 0; s < 4; s++) {
            float t = t0 + ((s == 0) ? 0.0f : (s == 3 ? DT : 0.5f*DT));

            // ========== A = Ue * W2 ==========
            ull AP[32];
            #pragma unroll
            for (int k = 0; k < 8; k++) {
                #pragma unroll
                for (int i = 0; i < 8; i++) {
                    ull d = (k & 1) ? dup_hi(UeP[i*4+(k>>1)]) : dup_lo(UeP[i*4+(k>>1)]);
                    #pragma unroll
                    for (int c = 0; c < 4; c++) {
                        ull w = w2p[k*4+c];
                        if (k == 0) AP[i*4+c] = mul2(d, w);
                        else        AP[i*4+c] = fma2(d, w, AP[i*4+c]);
                    }
                }
            }

            // ========== R' = (P^T - P) (unscaled) fused with s2 = <A, R v> ==========
            // R'[i][j] = <Ue_j, v_i> - <Ue_i, v_j>  for i<j
            // s2' accumulates Sum R'ij * (<A_i,v_j> - <A_j,v_i>) in packed form
            float Rt[28];
            ull s2a = 0ull, s2b = 0ull;
            #pragma unroll
            for (int i = 0; i < 8; i++) {
                ull vi[4];
                #pragma unroll
                for (int c = 0; c < 4; c++) vi[c] = sv[(i*4+c)*NT];
                #pragma unroll
                for (int j = i+1; j < 8; j++) {
                    ull vj[4];
                    #pragma unroll
                    for (int c = 0; c < 4; c++) vj[c] = sv[(j*4+c)*NT];
                    ull p1 = dotp(&UeP[j*4], vi);
                    ull p2 = dotp(&UeP[i*4], vj);
                    float r = hsum2(p1) - hsum2(p2);
                    Rt[TRI(i,j)] = r;
                    ull rd = dup_f(r);
                    ull q1 = dotp(&AP[i*4], vj);
                    ull q2 = dotp(&AP[j*4], vi);
                    s2a = fma2(rd, q1, s2a);
                    s2b = fma2(rd, q2, s2b);
                }
            }

            // ========== s1 = <Bv, R Ue> ==========
            ull s1a = 0ull, s1b = 0ull;
            #pragma unroll
            for (int i = 0; i < 8; i++) {
                ull bi[4];
                #pragma unroll
                for (int c = 0; c < 4; c++) bi[c] = sbv[(i*4+c)*NT];
                #pragma unroll
                for (int j = i+1; j < 8; j++) {
                    ull bj[4];
                    #pragma unroll
                    for (int c = 0; c < 4; c++) bj[c] = sbv[(j*4+c)*NT];
                    ull rd = dup_f(Rt[TRI(i,j)]);
                    ull q1 = dotp(&UeP[j*4], bi);
                    ull q2 = dotp(&UeP[i*4], bj);
                    s1a = fma2(rd, q1, s1a);
                    s1b = fma2(rd, q2, s1b);
                }
            }
            float kl = 0.5f * ((hsum2(s1a) - hsum2(s1b)) + (hsum2(s2a) - hsum2(s2b)));

            // ========== F = antisym(A Ue^T) + w0a + t*w1a, vel = F*Ue (incremental) ==========
            ull velP[32];
            #pragma unroll
            for (int c = 0; c < 32; c++) velP[c] = 0ull;
            #pragma unroll
            for (int i = 0; i < 8; i++) {
                #pragma unroll
                for (int j = i+1; j < 8; j++) {
                    ull m1 = dotp(&AP[i*4], &UeP[j*4]);   // M[i][j]
                    ull m2 = dotp(&AP[j*4], &UeP[i*4]);   // M[j][i]
                    float f = fmaf(t, w1a[i*8+j],
                                   fmaf(0.5f, hsum2(m1) - hsum2(m2), w0a[i*8+j]));
                    ull fd = dup_f(f);
                    ull fn = dup_f(-f);
                    #pragma unroll
                    for (int c = 0; c < 4; c++) {
                        velP[i*4+c] = fma2(fd, UeP[j*4+c], velP[i*4+c]);
                        velP[j*4+c] = fma2(fn, UeP[i*4+c], velP[j*4+c]);
                    }
                }
            }
            // ========== end rhs ==========

            if (s == 0) {
                lacc = kl;
                const ull hdt = dup_f(0.5f*DT);
                #pragma unroll
                for (int c = 0; c < 32; c++) {
                    sac[c*NT] = velP[c];
                    UeP[c] = fma2(hdt, velP[c], UeP[c]);     // UeP was U base
                }
            } else if (s == 1) {
                lacc = fmaf(2.0f, kl, lacc);
                const ull two = dup_f(2.0f), hdt = dup_f(0.5f*DT);
                #pragma unroll
                for (int c = 0; c < 32; c++) {
                    sac[c*NT] = fma2(two, velP[c], sac[c*NT]);
                    UeP[c] = fma2(hdt, velP[c], sub[c*NT]);
                }
            } else if (s == 2) {
                lacc = fmaf(2.0f, kl, lacc);
                const ull two = dup_f(2.0f), fdt = dup_f(DT);
                #pragma unroll
                for (int c = 0; c < 32; c++) {
                    sac[c*NT] = fma2(two, velP[c], sac[c*NT]);
                    UeP[c] = fma2(fdt, velP[c], sub[c*NT]);
                }
            } else {
                logj = fmaf(DT/6.0f, lacc + kl, logj);
                const ull d6 = dup_f(DT/6.0f);
                #pragma unroll
                for (int c = 0; c < 32; c++) {
                    ull un = fma2(d6, add2(sac[c*NT], velP[c]), sub[c*NT]);
                    UeP[c] = un;
                    sub[c*NT] = un;
                }
            }
        }
    }

    // ---- write outputs: U then logj ----
    {
        ulonglong2* o2 = (ulonglong2*)(out + (size_t)gtid * 64);
        #pragma unroll
        for (int e = 0; e < 16; e++) {
            ulonglong2 w;
            w.x = UeP[2*e]; w.y = UeP[2*e+1];
            o2[e] = w;
        }
        out[(size_t)B * 64 + gtid] = logj;
    }
}

extern "C" void kernel_launch(void* const* d_in, const int* in_sizes, int n_in,
                              void* d_out, int out_size)
{
    const float* U0  = (const float*)d_in[0];
    const float* eps = (const float*)d_in[1];
    const float* W0  = (const float*)d_in[2];
    const float* W1  = (const float*)d_in[3];
    const float* W2  = (const float*)d_in[4];
    float* out = (float*)d_out;

    int B = in_sizes[0] / 64;
    size_t shmem = (size_t)(96 + 4 * 32 * NT) * sizeof(ull);   // ~193 KB
    cudaFuncSetAttribute(adj_lie_kernel,
                         cudaFuncAttributeMaxDynamicSharedMemorySize, (int)shmem);
    int grid = (B + NT - 1) / NT;
    adj_lie_kernel<<<grid, NT, shmem>>>(U0, eps, W0, W1, W2, out, B);
}

// round 7
// speedup vs baseline: 1.3198x; 1.1676x over previous
#include <cuda_runtime.h>

typedef unsigned long long ull;

#define NT 192
#define NSTEPS 16
#define DT (1.0f/16.0f)
// upper-triangle index for i<j, 8x8
#define TRI(i,j) ((i)*7 - (i)*((i)-1)/2 + (j) - (i) - 1)

__device__ __forceinline__ ull fma2(ull a, ull b, ull c){
    ull d; asm("fma.rn.f32x2 %0,%1,%2,%3;" : "=l"(d) : "l"(a),"l"(b),"l"(c)); return d;
}
__device__ __forceinline__ ull mul2(ull a, ull b){
    ull d; asm("mul.rn.f32x2 %0,%1,%2;" : "=l"(d) : "l"(a),"l"(b)); return d;
}
__device__ __forceinline__ ull add2(ull a, ull b){
    ull d; asm("add.rn.f32x2 %0,%1,%2;" : "=l"(d) : "l"(a),"l"(b)); return d;
}
__device__ __forceinline__ ull sub2(ull a, ull b){
    ull d; asm("sub.rn.f32x2 %0,%1,%2;" : "=l"(d) : "l"(a),"l"(b)); return d;
}
__device__ __forceinline__ float hsum2(ull a){
    float lo,hi; asm("mov.b64 {%0,%1},%2;" : "=f"(lo),"=f"(hi) : "l"(a)); return lo+hi;
}
__device__ __forceinline__ ull dup_f(float x){
    ull r; asm("mov.b64 %0,{%1,%1};" : "=l"(r) : "f"(x)); return r;
}
__device__ __forceinline__ ull dup_lo(ull a){
    ull r; asm("{.reg .f32 l,h; mov.b64 {l,h},%1; mov.b64 %0,{l,l};}" : "=l"(r) : "l"(a)); return r;
}
__device__ __forceinline__ ull dup_hi(ull a){
    ull r; asm("{.reg .f32 l,h; mov.b64 {l,h},%1; mov.b64 %0,{h,h};}" : "=l"(r) : "l"(a)); return r;
}
__device__ __forceinline__ ull pack2(float lo, float hi){
    ull r; asm("mov.b64 %0,{%1,%2};" : "=l"(r) : "f"(lo),"f"(hi)); return r;
}
__device__ __forceinline__ void unp2(ull a, float& lo, float& hi){
    asm("mov.b64 {%0,%1},%2;" : "=f"(lo),"=f"(hi) : "l"(a));
}
// packed dot of two 8-float rows (4 ull each): returns packed partial sums
__device__ __forceinline__ ull dotp(const ull* a, const ull* b){
    ull s = mul2(a[0],b[0]);
    s = fma2(a[1],b[1],s);
    s = fma2(a[2],b[2],s);
    s = fma2(a[3],b[3],s);
    return s;
}

extern "C" __global__ void __launch_bounds__(NT, 1)
adj_lie_kernel(const float* __restrict__ U0, const float* __restrict__ eps,
               const float* __restrict__ W0, const float* __restrict__ W1,
               const float* __restrict__ W2, float* __restrict__ out, int B)
{
    extern __shared__ ull shl[];
    ull* w2c  = shl;            // 32 : W2 column-packed: w2c[k*4+c] = (W2[2c][k], W2[2c+1][k])
    ull* w01  = shl + 32;       // 28 : (w0a_ij, w1a_ij) per TRI pair
    ull* svb  = shl + 64;               // [32][NT] : v (eps) rows packed
    ull* sgvb = svb  + 32*NT;           // [32][NT] : gv_j = W2 v_j^T rows packed
    ull* subb = sgvb + 32*NT;           // [32][NT] : U base
    ull* sacb = subb + 32*NT;           // [32][NT] : RK4 accumulator

    const int tid  = threadIdx.x;
    const int gtid = blockIdx.x * NT + tid;

    if (tid < 32) {
        int k = tid >> 2, c = tid & 3;
        w2c[tid] = pack2(W2[(2*c)*8 + k], W2[(2*c+1)*8 + k]);
    }
    if (tid < 64) {
        int i = tid >> 3, j = tid & 7;
        if (i < j) {
            w01[TRI(i,j)] = pack2(0.5f * (W0[i*8+j] - W0[j*8+i]),
                                  0.5f * (W1[i*8+j] - W1[j*8+i]));
        }
    }
    __syncthreads();

    if (gtid >= B) return;

    ull* sv  = svb  + tid;
    ull* sgv = sgvb + tid;
    ull* sub = subb + tid;
    ull* sac = sacb + tid;

    // ---- load U0 (regs + shared base) ----
    ull UeP[32];
    {
        const ulonglong2* u2 = (const ulonglong2*)(U0 + (size_t)gtid * 64);
        #pragma unroll
        for (int e = 0; e < 16; e++) {
            ulonglong2 u = u2[e];
            UeP[2*e] = u.x; UeP[2*e+1] = u.y;
        }
        #pragma unroll
        for (int c = 0; c < 32; c++) sub[c*NT] = UeP[c];
    }

    // ---- load eps: store v rows, and gv_j = W2 v_j^T (constant over integration) ----
    {
        const ulonglong2* e2 = (const ulonglong2*)(eps + (size_t)gtid * 64);
        #pragma unroll
        for (int j = 0; j < 8; j++) {
            ulonglong2 a = e2[2*j], b = e2[2*j+1];
            ull vr[4] = {a.x, a.y, b.x, b.y};
            #pragma unroll
            for (int c = 0; c < 4; c++) sv[(j*4+c)*NT] = vr[c];
            ull acc[4];
            #pragma unroll
            for (int k = 0; k < 8; k++) {
                ull d = (k & 1) ? dup_hi(vr[k>>1]) : dup_lo(vr[k>>1]);
                #pragma unroll
                for (int c = 0; c < 4; c++)
                    acc[c] = (k == 0) ? mul2(d, w2c[c]) : fma2(d, w2c[k*4+c], acc[c]);
            }
            #pragma unroll
            for (int c = 0; c < 4; c++) sgv[(j*4+c)*NT] = acc[c];
        }
    }

    float logj = 0.0f, lacc = 0.0f;

    #pragma unroll 1
    for (int step = 0; step < NSTEPS; step++) {
        float t0 = (float)step * DT;
        #pragma unroll 1
        for (int s = 0; s < 4; s++) {
            float t = t0 + ((s == 0) ? 0.0f : (s == 3 ? DT : 0.5f*DT));

            float kl;
            float fv[28];
            ull velP[32];
            {
                // ===== G_j = W2 * Ue_j^T  (packed over output index) =====
                ull GP[32];
                #pragma unroll
                for (int j = 0; j < 8; j++) {
                    #pragma unroll
                    for (int k = 0; k < 8; k++) {
                        ull d = (k & 1) ? dup_hi(UeP[j*4+(k>>1)]) : dup_lo(UeP[j*4+(k>>1)]);
                        #pragma unroll
                        for (int c = 0; c < 4; c++)
                            GP[j*4+c] = (k == 0) ? mul2(d, w2c[c])
                                                 : fma2(d, w2c[k*4+c], GP[j*4+c]);
                    }
                }

                // ===== fused pair loop: r, s1, s2, f =====
                ull s1p = 0ull, s2p = 0ull;
                #pragma unroll
                for (int i = 0; i < 7; i++) {
                    ull vi[4], gvi[4];
                    #pragma unroll
                    for (int c = 0; c < 4; c++) { vi[c] = sv[(i*4+c)*NT]; gvi[c] = sgv[(i*4+c)*NT]; }
                    #pragma unroll
                    for (int j = i+1; j < 8; j++) {
                        ull vj[4], gvj[4];
                        #pragma unroll
                        for (int c = 0; c < 4; c++) { vj[c] = sv[(j*4+c)*NT]; gvj[c] = sgv[(j*4+c)*NT]; }

                        // r = <Ue_j, v_i> - <Ue_i, v_j>  (unscaled)
                        ull pr = sub2(dotp(&UeP[j*4], vi), dotp(&UeP[i*4], vj));
                        float r = hsum2(pr);
                        ull rd = dup_f(r);
                        // s1 += r * (<G_j, v_i> - <G_i, v_j>)
                        s1p = fma2(rd, sub2(dotp(&GP[j*4], vi), dotp(&GP[i*4], vj)), s1p);
                        // s2 += r * (<Ue_i, gv_j> - <Ue_j, gv_i>)
                        s2p = fma2(rd, sub2(dotp(&UeP[i*4], gvj), dotp(&UeP[j*4], gvi)), s2p);
                        // f = 0.5*(M[i][j]-M[j][i]) + w0a + t*w1a,  M[i][j] = <Ue_i, G_j>
                        float dM = hsum2(sub2(dotp(&UeP[i*4], &GP[j*4]), dotp(&UeP[j*4], &GP[i*4])));
                        float w0, w1; unp2(w01[TRI(i,j)], w0, w1);
                        fv[TRI(i,j)] = fmaf(t, w1, fmaf(0.5f, dM, w0));
                    }
                }
                kl = 0.5f * (hsum2(s1p) + hsum2(s2p));
            }   // GP dead here

            // ===== vel = F * Ue, F antisymmetric from fv =====
            #pragma unroll
            for (int c = 0; c < 32; c++) velP[c] = 0ull;
            #pragma unroll
            for (int i = 0; i < 7; i++) {
                #pragma unroll
                for (int j = i+1; j < 8; j++) {
                    float f = fv[TRI(i,j)];
                    ull fd = dup_f(f);
                    ull fn = dup_f(-f);
                    #pragma unroll
                    for (int c = 0; c < 4; c++) {
                        velP[i*4+c] = fma2(fd, UeP[j*4+c], velP[i*4+c]);
                        velP[j*4+c] = fma2(fn, UeP[i*4+c], velP[j*4+c]);
                    }
                }
            }

            // ===== RK4 stage update =====
            if (s == 0) {
                lacc = kl;
                const ull hdt = dup_f(0.5f*DT);
                #pragma unroll
                for (int c = 0; c < 32; c++) {
                    sac[c*NT] = velP[c];
                    UeP[c] = fma2(hdt, velP[c], UeP[c]);     // UeP was U base
                }
            } else if (s == 1) {
                lacc = fmaf(2.0f, kl, lacc);
                const ull two = dup_f(2.0f), hdt = dup_f(0.5f*DT);
                #pragma unroll
                for (int c = 0; c < 32; c++) {
                    sac[c*NT] = fma2(two, velP[c], sac[c*NT]);
                    UeP[c] = fma2(hdt, velP[c], sub[c*NT]);
                }
            } else if (s == 2) {
                lacc = fmaf(2.0f, kl, lacc);
                const ull two = dup_f(2.0f), fdt = dup_f(DT);
                #pragma unroll
                for (int c = 0; c < 32; c++) {
                    sac[c*NT] = fma2(two, velP[c], sac[c*NT]);
                    UeP[c] = fma2(fdt, velP[c], sub[c*NT]);
                }
            } else {
                logj = fmaf(DT/6.0f, lacc + kl, logj);
                const ull d6 = dup_f(DT/6.0f);
                #pragma unroll
                for (int c = 0; c < 32; c++) {
                    ull un = fma2(d6, add2(sac[c*NT], velP[c]), sub[c*NT]);
                    UeP[c] = un;
                    sub[c*NT] = un;
                }
            }
        }
    }

    // ---- write outputs: U then logj ----
    {
        ulonglong2* o2 = (ulonglong2*)(out + (size_t)gtid * 64);
        #pragma unroll
        for (int e = 0; e < 16; e++) {
            ulonglong2 w;
            w.x = UeP[2*e]; w.y = UeP[2*e+1];
            o2[e] = w;
        }
        out[(size_t)B * 64 + gtid] = logj;
    }
}

extern "C" void kernel_launch(void* const* d_in, const int* in_sizes, int n_in,
                              void* d_out, int out_size)
{
    const float* U0  = (const float*)d_in[0];
    const float* eps = (const float*)d_in[1];
    const float* W0  = (const float*)d_in[2];
    const float* W1  = (const float*)d_in[3];
    const float* W2  = (const float*)d_in[4];
    float* out = (float*)d_out;

    int B = in_sizes[0] / 64;
    size_t shmem = (size_t)(64 + 4 * 32 * NT) * sizeof(ull);   // ~192.6 KB
    cudaFuncSetAttribute(adj_lie_kernel,
                         cudaFuncAttributeMaxDynamicSharedMemorySize, (int)shmem);
    int grid = (B + NT - 1) / NT;
    adj_lie_kernel<<<grid, NT, shmem>>>(U0, eps, W0, W1, W2, out, B);
}